// round 1
// baseline (speedup 1.0000x reference)
#include <cuda_runtime.h>
#include <cstdint>
#include <cstddef>

// Problem dims
#define NB   128     // batch
#define NT   256     // time steps
#define HD   1024    // hidden
#define IN   150     // input feature (J*D)
#define NC   60      // classes
#define G4   4096    // 4*HD

// Tile config
#define TM   64      // batch tile
#define TU   8       // hidden-unit tile
#define TN   32      // gate rows per CTA = 4 gates * TU
#define TK   16
#define NTHREADS 128

// ---------------- persistent device state (sanctioned scratch) ----------------
__device__ float g_h1[2][NB * HD];
__device__ float g_h2[2][NB * HD];
__device__ float g_c1[NB * HD];
__device__ float g_c2[NB * HD];
__device__ float g_bias1[G4];
__device__ float g_bias2[G4];

__device__ __forceinline__ float sigf(float x) { return 1.0f / (1.0f + expf(-x)); }

// ---------------- init: copy initial state, combine biases ----------------
__global__ void init_kernel(const float* __restrict__ h1, const float* __restrict__ c1,
                            const float* __restrict__ h2, const float* __restrict__ c2,
                            const float* __restrict__ bih1, const float* __restrict__ bhh1,
                            const float* __restrict__ bih2, const float* __restrict__ bhh2) {
    int i = blockIdx.x * blockDim.x + threadIdx.x;
    if (i < NB * HD) {
        g_h1[0][i] = h1[i];
        g_c1[i]    = c1[i];
        g_h2[0][i] = h2[i];
        g_c2[i]    = c2[i];
    }
    if (i < G4) {
        g_bias1[i] = bih1[i] + bhh1[i];
        g_bias2[i] = bih2[i] + bhh2[i];
    }
}

// ---------------- fused LSTM step (one layer per launch) ----------------
// phase 0: gates1 = h1[cur] @ Whh1^T + x_t @ Wih1^T + bias1 -> update (h1[cur^1], c1)
// phase 1: gates2 = h1[cur^1] @ Wih2^T + h2[cur] @ Whh2^T + bias2 -> update (h2[cur^1], c2)
// CTA computes a TM x TN tile of gates where TN = 4 gates x TU units, then applies
// the cell nonlinearity for its (batch-slice, unit-slice) and writes h/c directly.
__global__ __launch_bounds__(NTHREADS)
void lstm_step_kernel(int t, int phase,
                      const float* __restrict__ x,
                      const float* __restrict__ Wih1, const float* __restrict__ Whh1,
                      const float* __restrict__ Wih2, const float* __restrict__ Whh2) {
    __shared__ float As[TK][TM + 4];
    __shared__ float Bs[TK][TN + 4];
    __shared__ float Gs[TN][TM + 1];

    const int cur = t & 1;
    const float *A0, *A1, *W0, *W1, *bias;
    float *cst, *hout;
    int lda0, lda1, K0, K1;
    if (phase == 0) {
        A0 = g_h1[cur];       lda0 = HD;      K0 = HD; W0 = Whh1;
        A1 = x + (size_t)t * IN; lda1 = NT * IN; K1 = IN; W1 = Wih1;
        bias = g_bias1; cst = g_c1; hout = g_h1[cur ^ 1];
    } else {
        A0 = g_h1[cur ^ 1];   lda0 = HD;      K0 = HD; W0 = Wih2;
        A1 = g_h2[cur];       lda1 = HD;      K1 = HD; W1 = Whh2;
        bias = g_bias2; cst = g_c2; hout = g_h2[cur ^ 1];
    }

    const int tid = threadIdx.x;
    const int tx  = tid & 15;    // m direction: 16 threads x 4 m
    const int ty  = tid >> 4;    // n direction: 8 threads x 4 n
    const int m0  = blockIdx.x * TM;
    const int u0  = blockIdx.y * TU;

    // global->smem load assignments
    const int arow  = tid >> 1;            // 0..63 (batch row within tile)
    const int akoff = (tid & 1) * 8;       // k offsets [akoff, akoff+8)
    const int brow  = tid >> 2;            // 0..31 (gate row within tile)
    const int bkoff = (tid & 3) * 4;       // k offsets [bkoff, bkoff+4)
    const int brW   = (brow >> 3) * HD + u0 + (brow & 7);  // global W row

    float acc[4][4];
#pragma unroll
    for (int i = 0; i < 4; i++)
#pragma unroll
        for (int j = 0; j < 4; j++) acc[i][j] = 0.0f;

    const int nk0 = (K0 + TK - 1) / TK;
    const int nk1 = (K1 + TK - 1) / TK;
    const int ntiles = nk0 + nk1;

    float ra[8], rb[4];

    auto fetch = [&](int tile) {
        const float* A; const float* W; int lda, K, k0;
        if (tile < nk0) { A = A0; W = W0; lda = lda0; K = K0; k0 = tile * TK; }
        else            { A = A1; W = W1; lda = lda1; K = K1; k0 = (tile - nk0) * TK; }
        const bool full = (k0 + TK <= K);

        const size_t arowoff = (size_t)(m0 + arow) * lda;
        const bool avec = full &&
            (((uintptr_t)A | (uintptr_t)((size_t)lda * 4)) & 15) == 0;
        if (avec) {
            const float4* ap = (const float4*)(A + arowoff + k0 + akoff);
            float4 v0 = ap[0];
            float4 v1 = ap[1];
            ra[0] = v0.x; ra[1] = v0.y; ra[2] = v0.z; ra[3] = v0.w;
            ra[4] = v1.x; ra[5] = v1.y; ra[6] = v1.z; ra[7] = v1.w;
        } else {
#pragma unroll
            for (int i = 0; i < 8; i++) {
                int k = k0 + akoff + i;
                ra[i] = (k < K) ? __ldg(A + arowoff + k) : 0.0f;
            }
        }

        const size_t browoff = (size_t)brW * K;
        const bool wvec = full &&
            (((uintptr_t)W | (uintptr_t)((size_t)K * 4)) & 15) == 0;
        if (wvec) {
            float4 v = *(const float4*)(W + browoff + k0 + bkoff);
            rb[0] = v.x; rb[1] = v.y; rb[2] = v.z; rb[3] = v.w;
        } else {
#pragma unroll
            for (int i = 0; i < 4; i++) {
                int k = k0 + bkoff + i;
                rb[i] = (k < K) ? __ldg(W + browoff + k) : 0.0f;
            }
        }
    };

    fetch(0);
    for (int tile = 0; tile < ntiles; tile++) {
        __syncthreads();
#pragma unroll
        for (int i = 0; i < 8; i++) As[akoff + i][arow] = ra[i];
#pragma unroll
        for (int i = 0; i < 4; i++) Bs[bkoff + i][brow] = rb[i];
        __syncthreads();
        if (tile + 1 < ntiles) fetch(tile + 1);
#pragma unroll
        for (int kk = 0; kk < TK; kk++) {
            float4 av = *(const float4*)&As[kk][tx * 4];
            float4 bv = *(const float4*)&Bs[kk][ty * 4];
            acc[0][0] += av.x * bv.x; acc[0][1] += av.x * bv.y;
            acc[0][2] += av.x * bv.z; acc[0][3] += av.x * bv.w;
            acc[1][0] += av.y * bv.x; acc[1][1] += av.y * bv.y;
            acc[1][2] += av.y * bv.z; acc[1][3] += av.y * bv.w;
            acc[2][0] += av.z * bv.x; acc[2][1] += av.z * bv.y;
            acc[2][2] += av.z * bv.z; acc[2][3] += av.z * bv.w;
            acc[3][0] += av.w * bv.x; acc[3][1] += av.w * bv.y;
            acc[3][2] += av.w * bv.z; acc[3][3] += av.w * bv.w;
        }
    }
    __syncthreads();

    // stage gates (+bias) to smem, grouped for cell update
#pragma unroll
    for (int j = 0; j < 4; j++) {
        int nl = ty * 4 + j;
        int g  = nl >> 3;
        int du = nl & 7;
        float bv = bias[g * HD + u0 + du];
#pragma unroll
        for (int i = 0; i < 4; i++) Gs[nl][tx * 4 + i] = acc[i][j] + bv;
    }
    __syncthreads();

    // cell update: TM*TU = 512 cells, 4 per thread
#pragma unroll
    for (int r = 0; r < (TM * TU) / NTHREADS; r++) {
        int idx = tid + r * NTHREADS;
        int u   = idx >> 6;       // 0..7
        int ml  = idx & 63;       // 0..63
        float ig = Gs[u][ml];
        float fg = Gs[8 + u][ml];
        float gg = Gs[16 + u][ml];
        float og = Gs[24 + u][ml];
        int off = (m0 + ml) * HD + (u0 + u);
        float c  = cst[off];
        float cn = sigf(fg) * c + sigf(ig) * tanhf(gg);
        cst[off]  = cn;
        hout[off] = sigf(og) * tanhf(cn);
    }
}

// ---------------- final FC: out = h2 @ Wfc^T + bfc ----------------
__global__ void fc_kernel(const float* __restrict__ Wfc, const float* __restrict__ bfc,
                          float* __restrict__ out) {
    int b = blockIdx.x;
    int c = blockIdx.y;
    int lane = threadIdx.x;
    const float* h = &g_h2[0][b * HD];
    const float* w = Wfc + (size_t)c * HD;
    float s = 0.0f;
    for (int k = lane; k < HD; k += 32) s += h[k] * w[k];
#pragma unroll
    for (int o = 16; o > 0; o >>= 1) s += __shfl_xor_sync(0xFFFFFFFFu, s, o);
    if (lane == 0) out[b * NC + c] = s + bfc[c];
}

// ---------------- launch ----------------
extern "C" void kernel_launch(void* const* d_in, const int* in_sizes, int n_in,
                              void* d_out, int out_size) {
    (void)in_sizes; (void)n_in; (void)out_size;
    const float* x    = (const float*)d_in[0];
    const float* h1   = (const float*)d_in[1];
    const float* c1   = (const float*)d_in[2];
    const float* h2   = (const float*)d_in[3];
    const float* c2   = (const float*)d_in[4];
    const float* Wih1 = (const float*)d_in[5];
    const float* Whh1 = (const float*)d_in[6];
    const float* bih1 = (const float*)d_in[7];
    const float* bhh1 = (const float*)d_in[8];
    const float* Wih2 = (const float*)d_in[9];
    const float* Whh2 = (const float*)d_in[10];
    const float* bih2 = (const float*)d_in[11];
    const float* bhh2 = (const float*)d_in[12];
    const float* Wfc  = (const float*)d_in[13];
    const float* bfc  = (const float*)d_in[14];
    float* out = (float*)d_out;

    init_kernel<<<(NB * HD + 255) / 256, 256>>>(h1, c1, h2, c2, bih1, bhh1, bih2, bhh2);

    dim3 grid(NB / TM, HD / TU);   // (2, 128)
    for (int t = 0; t < NT; t++) {
        lstm_step_kernel<<<grid, NTHREADS>>>(t, 0, x, Wih1, Whh1, Wih2, Whh2);
        lstm_step_kernel<<<grid, NTHREADS>>>(t, 1, x, Wih1, Whh1, Wih2, Whh2);
    }

    fc_kernel<<<dim3(NB, NC), 32>>>(Wfc, bfc, out);
}